// round 10
// baseline (speedup 1.0000x reference)
#include <cuda_runtime.h>
#include <cstdint>
#include <cstddef>

#define BZ   256
#define SEQ  512
#define INS  256
#define HID  256

// ---------------------------------------------------------------------------
// helpers
// ---------------------------------------------------------------------------
__device__ __forceinline__ void ffma2(unsigned long long &acc,
                                      unsigned long long a,
                                      unsigned long long b) {
    asm volatile("fma.rn.f32x2 %0, %1, %2, %0;" : "+l"(acc) : "l"(a), "l"(b));
}
__device__ __forceinline__ unsigned long long pack2(float x, float y) {
    unsigned long long r;
    asm("mov.b64 %0, {%1, %2};" : "=l"(r) : "f"(x), "f"(y));
    return r;
}
__device__ __forceinline__ float2 unpack2(unsigned long long v) {
    float2 f;
    asm("mov.b64 {%0, %1}, %2;" : "=f"(f.x), "=f"(f.y) : "l"(v));
    return f;
}
__device__ __forceinline__ float acc_sum(unsigned long long v) {
    float2 p = unpack2(v);
    return p.x + p.y;
}
// fast tanh: 1 - 2/(e^{2x}+1)  via ex2.approx + rcp.approx (~1e-7 abs err)
__device__ __forceinline__ float tanh_fast(float x) {
    float e;
    asm("ex2.approx.f32 %0, %1;" : "=f"(e) : "f"(x * 2.8853900817779268f));
    float r;
    asm("rcp.approx.f32 %0, %1;" : "=f"(r) : "f"(e + 1.0f));
    return fmaf(-2.0f, r, 1.0f);
}
__device__ __forceinline__ void bar_named(int id, int nthreads) {
    asm volatile("bar.sync %0, %1;" :: "r"(id), "r"(nthreads) : "memory");
}

// ---------------------------------------------------------------------------
// Kernel 1: XU = X @ U + bias -> decoder region of d_out.
// REVERTED to the R6 version (R9's pre-duplicated-Xs variant regressed ~65us:
// it traded FMA-pipe MOVs for 4x LDS instruction count — wrong pipe).
// ---------------------------------------------------------------------------
__global__ void __launch_bounds__(256, 2) xu_kernel(
    const float* __restrict__ X, const float* __restrict__ U,
    const float* __restrict__ bias, float* __restrict__ C)
{
    __shared__ float Xs[2][16][128];
    __shared__ float Us[2][16][128];

    const int tid    = threadIdx.x;
    const int m_base = blockIdx.x * 128;
    const int n_base = blockIdx.y * 128;
    const int tx = tid & 15;
    const int ty = tid >> 4;
    const int m0 = ty * 8;
    const int n0 = tx * 8;

    const int lmx = tid >> 1;
    const int lkx = (tid & 1) * 8;
    const int lku = tid >> 4;
    const int lnu = (tid & 15) * 8;

    const float* Xg = X + (size_t)(m_base + lmx) * 256 + lkx;
    const float* Ug = U + (size_t)lku * 256 + n_base + lnu;

    float4 xa = *(const float4*)(Xg + 0);
    float4 xb = *(const float4*)(Xg + 4);
    float4 ua = *(const float4*)(Ug + 0);
    float4 ub = *(const float4*)(Ug + 4);

    int buf = 0;
    Xs[0][lkx + 0][lmx] = xa.x;  Xs[0][lkx + 1][lmx] = xa.y;
    Xs[0][lkx + 2][lmx] = xa.z;  Xs[0][lkx + 3][lmx] = xa.w;
    Xs[0][lkx + 4][lmx] = xb.x;  Xs[0][lkx + 5][lmx] = xb.y;
    Xs[0][lkx + 6][lmx] = xb.z;  Xs[0][lkx + 7][lmx] = xb.w;
    *(float4*)&Us[0][lku][lnu]     = ua;
    *(float4*)&Us[0][lku][lnu + 4] = ub;
    __syncthreads();

    unsigned long long acc[8][4];
#pragma unroll
    for (int i = 0; i < 8; i++)
#pragma unroll
        for (int j = 0; j < 4; j++) acc[i][j] = 0ULL;

    for (int kt = 0; kt < 16; kt++) {
        if (kt < 15) {
            const float* Xg2 = Xg + (kt + 1) * 16;
            const float* Ug2 = Ug + (size_t)(kt + 1) * 16 * 256;
            xa = *(const float4*)(Xg2 + 0);
            xb = *(const float4*)(Xg2 + 4);
            ua = *(const float4*)(Ug2 + 0);
            ub = *(const float4*)(Ug2 + 4);
        }
#pragma unroll
        for (int k = 0; k < 16; k++) {
            float a[8];
            *(float4*)&a[0] = *(const float4*)&Xs[buf][k][m0];
            *(float4*)&a[4] = *(const float4*)&Xs[buf][k][m0 + 4];
            ulonglong2 bq0 = *(const ulonglong2*)&Us[buf][k][n0];
            ulonglong2 bq1 = *(const ulonglong2*)&Us[buf][k][n0 + 4];
            unsigned long long bb[4] = {bq0.x, bq0.y, bq1.x, bq1.y};
#pragma unroll
            for (int i = 0; i < 8; i++) {
                unsigned long long a2 = pack2(a[i], a[i]);
                ffma2(acc[i][0], a2, bb[0]);
                ffma2(acc[i][1], a2, bb[1]);
                ffma2(acc[i][2], a2, bb[2]);
                ffma2(acc[i][3], a2, bb[3]);
            }
        }
        if (kt < 15) {
            int nb = buf ^ 1;
            Xs[nb][lkx + 0][lmx] = xa.x;  Xs[nb][lkx + 1][lmx] = xa.y;
            Xs[nb][lkx + 2][lmx] = xa.z;  Xs[nb][lkx + 3][lmx] = xa.w;
            Xs[nb][lkx + 4][lmx] = xb.x;  Xs[nb][lkx + 5][lmx] = xb.y;
            Xs[nb][lkx + 6][lmx] = xb.z;  Xs[nb][lkx + 7][lmx] = xb.w;
            *(float4*)&Us[nb][lku][lnu]     = ua;
            *(float4*)&Us[nb][lku][lnu + 4] = ub;
            __syncthreads();
            buf = nb;
        }
    }

    float b8[8];
    *(float4*)&b8[0] = *(const float4*)(bias + n_base + n0);
    *(float4*)&b8[4] = *(const float4*)(bias + n_base + n0 + 4);
#pragma unroll
    for (int i = 0; i < 8; i++) {
        float* Cr = C + (size_t)(m_base + m0 + i) * 256 + n_base + n0;
#pragma unroll
        for (int j = 0; j < 4; j++) {
            float2 p = unpack2(acc[i][j]);
            p.x += b8[2 * j];
            p.y += b8[2 * j + 1];
            *(float2*)(Cr + 2 * j) = p;
        }
    }
}

// ---------------------------------------------------------------------------
// Kernel 2 (v8): 128 CTAs x 512 thr, 2 rows/CTA, V in regs (KREG=20) + SMEM
// (KSM=12, 96KB). Changes vs R9:
//  - Vsm layout [kw][c][j]: per-column k-pairs contiguous -> part B uses
//    LDS.128 (12/thread instead of 24 LDS.64). Conflict-free (verified:
//    8-lane phases hit banks {0,12,24,4,16,28,8,20}).
//  - h updated IN PLACE (no double buffer): pair {kw,kw+8} exclusively reads
//    AND writes slice h[32kw..+32); all reads precede bar#1, writes follow it,
//    named pair barrier orders writes before next step's reads.
//  - red stays double-buffered (named bar instead of 2nd full barrier).
// ---------------------------------------------------------------------------
#define KREG 20
#define KSM  12
#define VSM_U64S   (8 * 256 * (KSM/2))       // 12288 u64 = 96KB
#define RED_HALF   (8 * 2 * 256)             // 4096 floats = 16KB
#define RED_FLOATS (2 * RED_HALF)            // 32KB
#define HB_FLOATS  (2 * 256)                 // 2KB (in-place, single buffer)
#define RNN_SMEM_BYTES (VSM_U64S * 8 + (RED_FLOATS + HB_FLOATS) * 4)

__global__ void __launch_bounds__(512, 1)
rnn_kernel(const float* __restrict__ enc, const float* __restrict__ V,
           float* __restrict__ dec)
{
    extern __shared__ __align__(16) unsigned long long smem_u64[];
    unsigned long long* Vsm = smem_u64;                  // [8][256][KSM/2]
    float* red = (float*)(smem_u64 + VSM_U64S);          // [2][8][2][256]
    float* hb  = red + RED_FLOATS;                       // [2][256]

    const int tid = threadIdx.x;
    const int l   = tid & 31;
    const int w   = tid >> 5;
    const int kw  = w & 7;
    const int cw  = w >> 3;
    const int b0  = blockIdx.x * 2;
    const int K   = kw * 32;
    const int col = cw * 128 + l;

    // ---- V regs: k in [K, K+KREG), 4 cols/thread
    unsigned long long Vr[4][KREG / 2];
#pragma unroll
    for (int cc = 0; cc < 4; cc++) {
        const float* Vc = V + (size_t)K * HID + col + 32 * cc;
#pragma unroll
        for (int j = 0; j < KREG / 2; j++)
            Vr[cc][j] = pack2(Vc[(size_t)(2 * j) * HID],
                              Vc[(size_t)(2 * j + 1) * HID]);
    }
    // ---- V smem [kw][c][j]: k = kw*32 + KREG + 2j
    for (int idx = tid; idx < VSM_U64S; idx += 512) {
        int kw2 = idx / (256 * (KSM / 2));
        int rem = idx % (256 * (KSM / 2));
        int c   = rem / (KSM / 2);
        int j   = rem % (KSM / 2);
        int k   = kw2 * 32 + KREG + 2 * j;
        Vsm[idx] = pack2(V[(size_t)k * HID + c], V[(size_t)(k + 1) * HID + c]);
    }
    // ---- h0 (single buffer, in-place updates)
    hb[tid & 511] = enc[(size_t)b0 * HID + (tid & 511)];
    __syncthreads();

    // finalizer: warp w -> row fr = w>>3, col fc = (w&7)*32 + l  (== tid&255)
    const int fr = tid >> 8;
    const int fc = tid & 255;
    const size_t oBase = ((size_t)(b0 + fr) * SEQ) * HID + fc;

    const int rstore = kw * 512 + cw * 128 + l;   // + r*256 + 32*cc
    const int barid  = 1 + kw;
    const float* h0p = hb + K;
    const float* h1p = h0p + 256;
    // part-B V base for this thread's col group (cc adds 32*6 u64 = 192)
    const unsigned long long* vsb = Vsm + kw * (256 * (KSM / 2)) + col * (KSM / 2);

#pragma unroll 1
    for (int t = 0; t < SEQ; t++) {
        const float xu = dec[oBase + (size_t)t * HID];   // prefetch

        float* redb = red + (t & 1) * RED_HALF;

        unsigned long long acc[2][4];
#pragma unroll
        for (int r = 0; r < 2; r++)
#pragma unroll
            for (int cc = 0; cc < 4; cc++) acc[r][cc] = 0ULL;

        // ---- Part B first: SMEM V via LDS.128 (k-pairs contiguous per col)
#pragma unroll
        for (int i = 0; i < KSM / 4; i++) {              // 4 k per iter
            ulonglong2 h0 = *(const ulonglong2*)(h0p + KREG + 4 * i);
            ulonglong2 h1 = *(const ulonglong2*)(h1p + KREG + 4 * i);
#pragma unroll
            for (int cc = 0; cc < 4; cc++) {
                ulonglong2 v = *(const ulonglong2*)(vsb + cc * (32 * (KSM / 2)) + 2 * i);
                ffma2(acc[0][cc], h0.x, v.x);
                ffma2(acc[0][cc], h0.y, v.y);
                ffma2(acc[1][cc], h1.x, v.x);
                ffma2(acc[1][cc], h1.y, v.y);
            }
        }
        // ---- Part A: register V
#pragma unroll
        for (int i = 0; i < KREG / 4; i++) {
            ulonglong2 h0 = *(const ulonglong2*)(h0p + 4 * i);
            ulonglong2 h1 = *(const ulonglong2*)(h1p + 4 * i);
#pragma unroll
            for (int cc = 0; cc < 4; cc++) {
                ffma2(acc[0][cc], h0.x, Vr[cc][2 * i]);
                ffma2(acc[0][cc], h0.y, Vr[cc][2 * i + 1]);
                ffma2(acc[1][cc], h1.x, Vr[cc][2 * i]);
                ffma2(acc[1][cc], h1.y, Vr[cc][2 * i + 1]);
            }
        }

        // ---- stage partials: red[t&1][kw][r][cw*128 + 32cc + l]
#pragma unroll
        for (int r = 0; r < 2; r++)
#pragma unroll
            for (int cc = 0; cc < 4; cc++)
                redb[rstore + r * 256 + 32 * cc] = acc_sum(acc[r][cc]);
        __syncthreads();                      // bar#1 (full): partials + h reads done

        // ---- finalize: 8-way reduce over kw', tanh, store
        float s = 0.f;
#pragma unroll
        for (int ww = 0; ww < 8; ww++)
            s += redb[ww * 512 + fr * 256 + fc];
        const float v = tanh_fast(s + xu);

        dec[oBase + (size_t)t * HID] = v;

        hb[fr * 256 + fc] = v;               // in-place: slice kw, pair-owned
        bar_named(barid, 64);                // pair {kw, kw+8}: h slice ready
    }
}

// ---------------------------------------------------------------------------
// launch
// ---------------------------------------------------------------------------
extern "C" void kernel_launch(void* const* d_in, const int* in_sizes, int n_in,
                              void* d_out, int out_size)
{
    const float* enc  = (const float*)d_in[0];
    const float* xdec = (const float*)d_in[1];
    const float* U    = (const float*)d_in[2];
    const float* V    = (const float*)d_in[3];
    const float* b    = (const float*)d_in[4];

    float* out = (float*)d_out;
    float* dec = out + (size_t)BZ * HID;

    cudaMemcpyAsync(out, enc, (size_t)BZ * HID * sizeof(float),
                    cudaMemcpyDeviceToDevice, 0);

    xu_kernel<<<dim3((BZ * SEQ) / 128, HID / 128), 256>>>(xdec, U, b, dec);

    cudaFuncSetAttribute(rnn_kernel,
                         cudaFuncAttributeMaxDynamicSharedMemorySize,
                         RNN_SMEM_BYTES);
    rnn_kernel<<<128, 512, RNN_SMEM_BYTES>>>(enc, V, dec);
}

// round 11
// speedup vs baseline: 1.0685x; 1.0685x over previous
#include <cuda_runtime.h>
#include <cstdint>
#include <cstddef>

#define BZ   256
#define SEQ  512
#define INS  256
#define HID  256

// ---------------------------------------------------------------------------
// helpers
// ---------------------------------------------------------------------------
__device__ __forceinline__ void ffma2(unsigned long long &acc,
                                      unsigned long long a,
                                      unsigned long long b) {
    asm volatile("fma.rn.f32x2 %0, %1, %2, %0;" : "+l"(acc) : "l"(a), "l"(b));
}
__device__ __forceinline__ unsigned long long pack2(float x, float y) {
    unsigned long long r;
    asm("mov.b64 %0, {%1, %2};" : "=l"(r) : "f"(x), "f"(y));
    return r;
}
__device__ __forceinline__ float2 unpack2(unsigned long long v) {
    float2 f;
    asm("mov.b64 {%0, %1}, %2;" : "=f"(f.x), "=f"(f.y) : "l"(v));
    return f;
}
__device__ __forceinline__ float acc_sum(unsigned long long v) {
    float2 p = unpack2(v);
    return p.x + p.y;
}
// fast tanh: 1 - 2/(e^{2x}+1)  via ex2.approx + rcp.approx (~1e-7 abs err)
__device__ __forceinline__ float tanh_fast(float x) {
    float e;
    asm("ex2.approx.f32 %0, %1;" : "=f"(e) : "f"(x * 2.8853900817779268f));
    float r;
    asm("rcp.approx.f32 %0, %1;" : "=f"(r) : "f"(e + 1.0f));
    return fmaf(-2.0f, r, 1.0f);
}
__device__ __forceinline__ void bar_named(int id, int nthreads) {
    asm volatile("bar.sync %0, %1;" :: "r"(id), "r"(nthreads) : "memory");
}

// ---------------------------------------------------------------------------
// Kernel 1: XU = X @ U + bias -> decoder region of d_out.
// EXACT R6 version — measured best (~410us). Do not touch.
// ---------------------------------------------------------------------------
__global__ void __launch_bounds__(256, 2) xu_kernel(
    const float* __restrict__ X, const float* __restrict__ U,
    const float* __restrict__ bias, float* __restrict__ C)
{
    __shared__ float Xs[2][16][128];
    __shared__ float Us[2][16][128];

    const int tid    = threadIdx.x;
    const int m_base = blockIdx.x * 128;
    const int n_base = blockIdx.y * 128;
    const int tx = tid & 15;
    const int ty = tid >> 4;
    const int m0 = ty * 8;
    const int n0 = tx * 8;

    const int lmx = tid >> 1;
    const int lkx = (tid & 1) * 8;
    const int lku = tid >> 4;
    const int lnu = (tid & 15) * 8;

    const float* Xg = X + (size_t)(m_base + lmx) * 256 + lkx;
    const float* Ug = U + (size_t)lku * 256 + n_base + lnu;

    float4 xa = *(const float4*)(Xg + 0);
    float4 xb = *(const float4*)(Xg + 4);
    float4 ua = *(const float4*)(Ug + 0);
    float4 ub = *(const float4*)(Ug + 4);

    int buf = 0;
    Xs[0][lkx + 0][lmx] = xa.x;  Xs[0][lkx + 1][lmx] = xa.y;
    Xs[0][lkx + 2][lmx] = xa.z;  Xs[0][lkx + 3][lmx] = xa.w;
    Xs[0][lkx + 4][lmx] = xb.x;  Xs[0][lkx + 5][lmx] = xb.y;
    Xs[0][lkx + 6][lmx] = xb.z;  Xs[0][lkx + 7][lmx] = xb.w;
    *(float4*)&Us[0][lku][lnu]     = ua;
    *(float4*)&Us[0][lku][lnu + 4] = ub;
    __syncthreads();

    unsigned long long acc[8][4];
#pragma unroll
    for (int i = 0; i < 8; i++)
#pragma unroll
        for (int j = 0; j < 4; j++) acc[i][j] = 0ULL;

    for (int kt = 0; kt < 16; kt++) {
        if (kt < 15) {
            const float* Xg2 = Xg + (kt + 1) * 16;
            const float* Ug2 = Ug + (size_t)(kt + 1) * 16 * 256;
            xa = *(const float4*)(Xg2 + 0);
            xb = *(const float4*)(Xg2 + 4);
            ua = *(const float4*)(Ug2 + 0);
            ub = *(const float4*)(Ug2 + 4);
        }
#pragma unroll
        for (int k = 0; k < 16; k++) {
            float a[8];
            *(float4*)&a[0] = *(const float4*)&Xs[buf][k][m0];
            *(float4*)&a[4] = *(const float4*)&Xs[buf][k][m0 + 4];
            ulonglong2 bq0 = *(const ulonglong2*)&Us[buf][k][n0];
            ulonglong2 bq1 = *(const ulonglong2*)&Us[buf][k][n0 + 4];
            unsigned long long bb[4] = {bq0.x, bq0.y, bq1.x, bq1.y};
#pragma unroll
            for (int i = 0; i < 8; i++) {
                unsigned long long a2 = pack2(a[i], a[i]);
                ffma2(acc[i][0], a2, bb[0]);
                ffma2(acc[i][1], a2, bb[1]);
                ffma2(acc[i][2], a2, bb[2]);
                ffma2(acc[i][3], a2, bb[3]);
            }
        }
        if (kt < 15) {
            int nb = buf ^ 1;
            Xs[nb][lkx + 0][lmx] = xa.x;  Xs[nb][lkx + 1][lmx] = xa.y;
            Xs[nb][lkx + 2][lmx] = xa.z;  Xs[nb][lkx + 3][lmx] = xa.w;
            Xs[nb][lkx + 4][lmx] = xb.x;  Xs[nb][lkx + 5][lmx] = xb.y;
            Xs[nb][lkx + 6][lmx] = xb.z;  Xs[nb][lkx + 7][lmx] = xb.w;
            *(float4*)&Us[nb][lku][lnu]     = ua;
            *(float4*)&Us[nb][lku][lnu + 4] = ub;
            __syncthreads();
            buf = nb;
        }
    }

    float b8[8];
    *(float4*)&b8[0] = *(const float4*)(bias + n_base + n0);
    *(float4*)&b8[4] = *(const float4*)(bias + n_base + n0 + 4);
#pragma unroll
    for (int i = 0; i < 8; i++) {
        float* Cr = C + (size_t)(m_base + m0 + i) * 256 + n_base + n0;
#pragma unroll
        for (int j = 0; j < 4; j++) {
            float2 p = unpack2(acc[i][j]);
            p.x += b8[2 * j];
            p.y += b8[2 * j + 1];
            *(float2*)(Cr + 2 * j) = p;
        }
    }
}

// ---------------------------------------------------------------------------
// Kernel 2: EXACT R9 version (measured best: 582us) + encoder passthrough
// folded in (the enc value loaded for h0 is also stored to out, replacing the
// separate cudaMemcpyAsync graph node).
// 128 CTAs x 512 thr, 2 rows/CTA, V in regs (KREG=20) + SMEM (KSM=12, 96KB,
// layout [kw][j][c], LDS.64). red double-buffered; h double-buffered; full
// __syncthreads after partials; named pair barrier {kw, kw+8} after h store.
// [R10's Vsm-transpose-to-LDS.128 + in-place-h regressed 582->654: reverted.]
// ---------------------------------------------------------------------------
#define KREG 20
#define KSM  12
#define VSM_U64S   (8 * (KSM/2) * 256)       // 12288 u64 = 96KB
#define RED_HALF   (8 * 2 * 256)             // 4096 floats = 16KB
#define RED_FLOATS (2 * RED_HALF)            // 32KB
#define HB_FLOATS  (2 * 2 * 256)             // 4KB
#define RNN_SMEM_BYTES (VSM_U64S * 8 + (RED_FLOATS + HB_FLOATS) * 4)

__global__ void __launch_bounds__(512, 1)
rnn_kernel(const float* __restrict__ enc, const float* __restrict__ V,
           float* __restrict__ dec, float* __restrict__ outenc)
{
    extern __shared__ __align__(16) unsigned long long smem_u64[];
    unsigned long long* Vsm = smem_u64;                  // [8][KSM/2][256]
    float* red = (float*)(smem_u64 + VSM_U64S);          // [2][8][2][256]
    float* hb  = red + RED_FLOATS;                       // [2][2][256]

    const int tid = threadIdx.x;
    const int l   = tid & 31;
    const int w   = tid >> 5;
    const int kw  = w & 7;
    const int cw  = w >> 3;
    const int b0  = blockIdx.x * 2;
    const int K   = kw * 32;
    const int col = cw * 128 + l;

    unsigned long long Vr[4][KREG / 2];
#pragma unroll
    for (int cc = 0; cc < 4; cc++) {
        const float* Vc = V + (size_t)K * HID + col + 32 * cc;
#pragma unroll
        for (int j = 0; j < KREG / 2; j++)
            Vr[cc][j] = pack2(Vc[(size_t)(2 * j) * HID],
                              Vc[(size_t)(2 * j + 1) * HID]);
    }
    for (int idx = tid; idx < VSM_U64S; idx += 512) {
        int kk  = idx >> 8;
        int c   = idx & 255;
        int kw2 = kk / (KSM / 2);
        int j   = kk % (KSM / 2);
        int k   = kw2 * 32 + KREG + 2 * j;
        Vsm[idx] = pack2(V[(size_t)k * HID + c], V[(size_t)(k + 1) * HID + c]);
    }
    // h0 + encoder passthrough (out poisoned by harness -> must write)
    {
        const float ev = enc[(size_t)b0 * HID + tid];
        hb[tid] = ev;
        outenc[(size_t)b0 * HID + tid] = ev;
    }
    __syncthreads();

    // finalizer: warp w -> row fr = w>>3, col fc = (w&7)*32 + l  (== tid&255)
    const int fr = tid >> 8;
    const int fc = tid & 255;
    const size_t oBase = ((size_t)(b0 + fr) * SEQ) * HID + fc;

    const int rstore = kw * 512 + cw * 128 + l;   // + r*256 + 32*cc
    const int barid  = 1 + kw;
    int cur = 0;

#pragma unroll 1
    for (int t = 0; t < SEQ; t++) {
        const float xu = dec[oBase + (size_t)t * HID];

        float* redb = red + (t & 1) * RED_HALF;
        const float* h0p = hb + cur * 512 + K;
        const float* h1p = h0p + 256;

        unsigned long long acc[2][4];
#pragma unroll
        for (int r = 0; r < 2; r++)
#pragma unroll
            for (int cc = 0; cc < 4; cc++) acc[r][cc] = 0ULL;

        // ---- Part B first: SMEM V (long-scoreboard loads early)
        const unsigned long long* vsb = Vsm + kw * ((KSM / 2) * 256) + col;
#pragma unroll
        for (int i = 0; i < KSM / 4; i++) {
            ulonglong2 h0 = *(const ulonglong2*)(h0p + KREG + 4 * i);
            ulonglong2 h1 = *(const ulonglong2*)(h1p + KREG + 4 * i);
#pragma unroll
            for (int cc = 0; cc < 4; cc++) {
                unsigned long long v0 = vsb[(2 * i) * 256 + 32 * cc];
                unsigned long long v1 = vsb[(2 * i + 1) * 256 + 32 * cc];
                ffma2(acc[0][cc], h0.x, v0);
                ffma2(acc[0][cc], h0.y, v1);
                ffma2(acc[1][cc], h1.x, v0);
                ffma2(acc[1][cc], h1.y, v1);
            }
        }
        // ---- Part A: register V
#pragma unroll
        for (int i = 0; i < KREG / 4; i++) {
            ulonglong2 h0 = *(const ulonglong2*)(h0p + 4 * i);
            ulonglong2 h1 = *(const ulonglong2*)(h1p + 4 * i);
#pragma unroll
            for (int cc = 0; cc < 4; cc++) {
                ffma2(acc[0][cc], h0.x, Vr[cc][2 * i]);
                ffma2(acc[0][cc], h0.y, Vr[cc][2 * i + 1]);
                ffma2(acc[1][cc], h1.x, Vr[cc][2 * i]);
                ffma2(acc[1][cc], h1.y, Vr[cc][2 * i + 1]);
            }
        }

        // ---- stage partials: red[t&1][kw][r][cw*128 + 32cc + l]
#pragma unroll
        for (int r = 0; r < 2; r++)
#pragma unroll
            for (int cc = 0; cc < 4; cc++)
                redb[rstore + r * 256 + 32 * cc] = acc_sum(acc[r][cc]);
        __syncthreads();                      // bar#1 (full)

        // ---- finalize: 8-way reduce over kw', tanh, store
        float s = 0.f;
#pragma unroll
        for (int ww = 0; ww < 8; ww++)
            s += redb[ww * 512 + fr * 256 + fc];
        const float v = tanh_fast(s + xu);

        dec[oBase + (size_t)t * HID] = v;

        const int nxt = cur ^ 1;
        hb[nxt * 512 + fr * 256 + fc] = v;
        bar_named(barid, 64);                 // pair {kw, kw+8}: h[nxt] ready
        cur = nxt;
    }
}

// ---------------------------------------------------------------------------
// launch
// ---------------------------------------------------------------------------
extern "C" void kernel_launch(void* const* d_in, const int* in_sizes, int n_in,
                              void* d_out, int out_size)
{
    const float* enc  = (const float*)d_in[0];
    const float* xdec = (const float*)d_in[1];
    const float* U    = (const float*)d_in[2];
    const float* V    = (const float*)d_in[3];
    const float* b    = (const float*)d_in[4];

    float* out = (float*)d_out;
    float* dec = out + (size_t)BZ * HID;

    xu_kernel<<<dim3((BZ * SEQ) / 128, HID / 128), 256>>>(xdec, U, b, dec);

    cudaFuncSetAttribute(rnn_kernel,
                         cudaFuncAttributeMaxDynamicSharedMemorySize,
                         RNN_SMEM_BYTES);
    rnn_kernel<<<128, 512, RNN_SMEM_BYTES>>>(enc, V, dec, out);
}

// round 12
// speedup vs baseline: 1.1844x; 1.1085x over previous
#include <cuda_runtime.h>
#include <cstdint>
#include <cstddef>

#define BZ   256
#define SEQ  512
#define INS  256
#define HID  256

// ---------------------------------------------------------------------------
// helpers
// ---------------------------------------------------------------------------
__device__ __forceinline__ void ffma2(unsigned long long &acc,
                                      unsigned long long a,
                                      unsigned long long b) {
    asm volatile("fma.rn.f32x2 %0, %1, %2, %0;" : "+l"(acc) : "l"(a), "l"(b));
}
__device__ __forceinline__ unsigned long long pack2(float x, float y) {
    unsigned long long r;
    asm("mov.b64 %0, {%1, %2};" : "=l"(r) : "f"(x), "f"(y));
    return r;
}
__device__ __forceinline__ float2 unpack2(unsigned long long v) {
    float2 f;
    asm("mov.b64 {%0, %1}, %2;" : "=f"(f.x), "=f"(f.y) : "l"(v));
    return f;
}
__device__ __forceinline__ float acc_sum(unsigned long long v) {
    float2 p = unpack2(v);
    return p.x + p.y;
}
// fast tanh: 1 - 2/(e^{2x}+1)  via ex2.approx + rcp.approx (~1e-7 abs err)
__device__ __forceinline__ float tanh_fast(float x) {
    float e;
    asm("ex2.approx.f32 %0, %1;" : "=f"(e) : "f"(x * 2.8853900817779268f));
    float r;
    asm("rcp.approx.f32 %0, %1;" : "=f"(r) : "f"(e + 1.0f));
    return fmaf(-2.0f, r, 1.0f);
}
__device__ __forceinline__ void bar_named(int id, int nthreads) {
    asm volatile("bar.sync %0, %1;" :: "r"(id), "r"(nthreads) : "memory");
}

// ---------------------------------------------------------------------------
// Kernel 1 (v2): XU = X @ U + bias -> decoder region of d_out.
// R11 diagnosis: old 8mx8n mapping had U-loads at 32B lane stride -> 4-way
// bank conflict (LDS 576 cyc/SM/k vs FMA floor 256) plus 32 MOV32/thread/k
// packing (a,a) pairs. New mapping:
//  - FFMA2 pairs run along M: Xs is m-contiguous so a-pairs (x[m],x[m+1])
//    load as native u64 — no packing at all on the a side.
//  - per-thread tile 16m x 4n; lane -> cols l*4..l*4+3: the b-load is ONE
//    LDS.128 with 32 consecutive 16B chunks — conflict-free by construction.
//  - b duplicated via only 4 pack2 per k (values reused across 8 m-pairs).
// LDS drops to ~128 cyc/SM/k << FMA 256 -> FMA-issue-bound (~126us model).
// Loaders, double-buffering, smem layout unchanged from the measured-good R6.
// ---------------------------------------------------------------------------
__global__ void __launch_bounds__(256, 2) xu_kernel(
    const float* __restrict__ X, const float* __restrict__ U,
    const float* __restrict__ bias, float* __restrict__ C)
{
    __shared__ float Xs[2][16][128];   // [k][m], m contiguous
    __shared__ float Us[2][16][128];   // [k][n], n contiguous

    const int tid    = threadIdx.x;
    const int m_base = blockIdx.x * 128;
    const int n_base = blockIdx.y * 128;
    const int l  = tid & 31;
    const int w  = tid >> 5;          // 8 warps
    const int m0 = w * 16;            // 16 m-rows per warp (all lanes share)
    const int n0 = l * 4;             // 4 n-cols per lane (consecutive)

    // loader mappings (unchanged)
    const int lmx = tid >> 1;
    const int lkx = (tid & 1) * 8;
    const int lku = tid >> 4;
    const int lnu = (tid & 15) * 8;

    const float* Xg = X + (size_t)(m_base + lmx) * 256 + lkx;
    const float* Ug = U + (size_t)lku * 256 + n_base + lnu;

    float4 xa = *(const float4*)(Xg + 0);
    float4 xb = *(const float4*)(Xg + 4);
    float4 ua = *(const float4*)(Ug + 0);
    float4 ub = *(const float4*)(Ug + 4);

    int buf = 0;
    Xs[0][lkx + 0][lmx] = xa.x;  Xs[0][lkx + 1][lmx] = xa.y;
    Xs[0][lkx + 2][lmx] = xa.z;  Xs[0][lkx + 3][lmx] = xa.w;
    Xs[0][lkx + 4][lmx] = xb.x;  Xs[0][lkx + 5][lmx] = xb.y;
    Xs[0][lkx + 6][lmx] = xb.z;  Xs[0][lkx + 7][lmx] = xb.w;
    *(float4*)&Us[0][lku][lnu]     = ua;
    *(float4*)&Us[0][lku][lnu + 4] = ub;
    __syncthreads();

    unsigned long long acc[8][4];      // [m-pair][n]; u64 = rows (2mp, 2mp+1)
#pragma unroll
    for (int i = 0; i < 8; i++)
#pragma unroll
        for (int j = 0; j < 4; j++) acc[i][j] = 0ULL;

    for (int kt = 0; kt < 16; kt++) {
        if (kt < 15) {
            const float* Xg2 = Xg + (kt + 1) * 16;
            const float* Ug2 = Ug + (size_t)(kt + 1) * 16 * 256;
            xa = *(const float4*)(Xg2 + 0);
            xb = *(const float4*)(Xg2 + 4);
            ua = *(const float4*)(Ug2 + 0);
            ub = *(const float4*)(Ug2 + 4);
        }
#pragma unroll
        for (int k = 0; k < 16; k++) {
            // b: 4 consecutive cols, ONE conflict-free LDS.128, dup via 4 pack2
            float4 u4 = *(const float4*)&Us[buf][k][n0];
            unsigned long long bd[4] = { pack2(u4.x, u4.x), pack2(u4.y, u4.y),
                                         pack2(u4.z, u4.z), pack2(u4.w, u4.w) };
            // a: 16 m-values = 8 native u64 pairs, broadcast LDS.128 x4
            ulonglong2 A0 = *(const ulonglong2*)&Xs[buf][k][m0];
            ulonglong2 A1 = *(const ulonglong2*)&Xs[buf][k][m0 + 4];
            ulonglong2 A2 = *(const ulonglong2*)&Xs[buf][k][m0 + 8];
            ulonglong2 A3 = *(const ulonglong2*)&Xs[buf][k][m0 + 12];
            unsigned long long am[8] = { A0.x, A0.y, A1.x, A1.y,
                                         A2.x, A2.y, A3.x, A3.y };
#pragma unroll
            for (int mp = 0; mp < 8; mp++) {
                ffma2(acc[mp][0], am[mp], bd[0]);
                ffma2(acc[mp][1], am[mp], bd[1]);
                ffma2(acc[mp][2], am[mp], bd[2]);
                ffma2(acc[mp][3], am[mp], bd[3]);
            }
        }
        if (kt < 15) {
            int nb = buf ^ 1;
            Xs[nb][lkx + 0][lmx] = xa.x;  Xs[nb][lkx + 1][lmx] = xa.y;
            Xs[nb][lkx + 2][lmx] = xa.z;  Xs[nb][lkx + 3][lmx] = xa.w;
            Xs[nb][lkx + 4][lmx] = xb.x;  Xs[nb][lkx + 5][lmx] = xb.y;
            Xs[nb][lkx + 6][lmx] = xb.z;  Xs[nb][lkx + 7][lmx] = xb.w;
            *(float4*)&Us[nb][lku][lnu]     = ua;
            *(float4*)&Us[nb][lku][lnu + 4] = ub;
            __syncthreads();
            buf = nb;
        }
    }

    // epilogue: rows m0+2mp (lo) and m0+2mp+1 (hi), cols n_base+n0..+3
    float4 bv = *(const float4*)(bias + n_base + n0);
#pragma unroll
    for (int mp = 0; mp < 8; mp++) {
        float2 p0 = unpack2(acc[mp][0]);
        float2 p1 = unpack2(acc[mp][1]);
        float2 p2 = unpack2(acc[mp][2]);
        float2 p3 = unpack2(acc[mp][3]);
        float* Cr0 = C + (size_t)(m_base + m0 + 2 * mp) * 256 + n_base + n0;
        float* Cr1 = Cr0 + 256;
        float4 o0 = { p0.x + bv.x, p1.x + bv.y, p2.x + bv.z, p3.x + bv.w };
        float4 o1 = { p0.y + bv.x, p1.y + bv.y, p2.y + bv.z, p3.y + bv.w };
        *(float4*)Cr0 = o0;
        *(float4*)Cr1 = o1;
    }
}

// ---------------------------------------------------------------------------
// Kernel 2: EXACT R11 version (measured 583us) — rnn + encoder passthrough.
// Do not touch.
// ---------------------------------------------------------------------------
#define KREG 20
#define KSM  12
#define VSM_U64S   (8 * (KSM/2) * 256)       // 12288 u64 = 96KB
#define RED_HALF   (8 * 2 * 256)             // 4096 floats = 16KB
#define RED_FLOATS (2 * RED_HALF)            // 32KB
#define HB_FLOATS  (2 * 2 * 256)             // 4KB
#define RNN_SMEM_BYTES (VSM_U64S * 8 + (RED_FLOATS + HB_FLOATS) * 4)

__global__ void __launch_bounds__(512, 1)
rnn_kernel(const float* __restrict__ enc, const float* __restrict__ V,
           float* __restrict__ dec, float* __restrict__ outenc)
{
    extern __shared__ __align__(16) unsigned long long smem_u64[];
    unsigned long long* Vsm = smem_u64;                  // [8][KSM/2][256]
    float* red = (float*)(smem_u64 + VSM_U64S);          // [2][8][2][256]
    float* hb  = red + RED_FLOATS;                       // [2][2][256]

    const int tid = threadIdx.x;
    const int l   = tid & 31;
    const int w   = tid >> 5;
    const int kw  = w & 7;
    const int cw  = w >> 3;
    const int b0  = blockIdx.x * 2;
    const int K   = kw * 32;
    const int col = cw * 128 + l;

    unsigned long long Vr[4][KREG / 2];
#pragma unroll
    for (int cc = 0; cc < 4; cc++) {
        const float* Vc = V + (size_t)K * HID + col + 32 * cc;
#pragma unroll
        for (int j = 0; j < KREG / 2; j++)
            Vr[cc][j] = pack2(Vc[(size_t)(2 * j) * HID],
                              Vc[(size_t)(2 * j + 1) * HID]);
    }
    for (int idx = tid; idx < VSM_U64S; idx += 512) {
        int kk  = idx >> 8;
        int c   = idx & 255;
        int kw2 = kk / (KSM / 2);
        int j   = kk % (KSM / 2);
        int k   = kw2 * 32 + KREG + 2 * j;
        Vsm[idx] = pack2(V[(size_t)k * HID + c], V[(size_t)(k + 1) * HID + c]);
    }
    // h0 + encoder passthrough (out poisoned by harness -> must write)
    {
        const float ev = enc[(size_t)b0 * HID + tid];
        hb[tid] = ev;
        outenc[(size_t)b0 * HID + tid] = ev;
    }
    __syncthreads();

    // finalizer: warp w -> row fr = w>>3, col fc = (w&7)*32 + l  (== tid&255)
    const int fr = tid >> 8;
    const int fc = tid & 255;
    const size_t oBase = ((size_t)(b0 + fr) * SEQ) * HID + fc;

    const int rstore = kw * 512 + cw * 128 + l;   // + r*256 + 32*cc
    const int barid  = 1 + kw;
    int cur = 0;

#pragma unroll 1
    for (int t = 0; t < SEQ; t++) {
        const float xu = dec[oBase + (size_t)t * HID];

        float* redb = red + (t & 1) * RED_HALF;
        const float* h0p = hb + cur * 512 + K;
        const float* h1p = h0p + 256;

        unsigned long long acc[2][4];
#pragma unroll
        for (int r = 0; r < 2; r++)
#pragma unroll
            for (int cc = 0; cc < 4; cc++) acc[r][cc] = 0ULL;

        // ---- Part B first: SMEM V (long-scoreboard loads early)
        const unsigned long long* vsb = Vsm + kw * ((KSM / 2) * 256) + col;
#pragma unroll
        for (int i = 0; i < KSM / 4; i++) {
            ulonglong2 h0 = *(const ulonglong2*)(h0p + KREG + 4 * i);
            ulonglong2 h1 = *(const ulonglong2*)(h1p + KREG + 4 * i);
#pragma unroll
            for (int cc = 0; cc < 4; cc++) {
                unsigned long long v0 = vsb[(2 * i) * 256 + 32 * cc];
                unsigned long long v1 = vsb[(2 * i + 1) * 256 + 32 * cc];
                ffma2(acc[0][cc], h0.x, v0);
                ffma2(acc[0][cc], h0.y, v1);
                ffma2(acc[1][cc], h1.x, v0);
                ffma2(acc[1][cc], h1.y, v1);
            }
        }
        // ---- Part A: register V
#pragma unroll
        for (int i = 0; i < KREG / 4; i++) {
            ulonglong2 h0 = *(const ulonglong2*)(h0p + 4 * i);
            ulonglong2 h1 = *(const ulonglong2*)(h1p + 4 * i);
#pragma unroll
            for (int cc = 0; cc < 4; cc++) {
                ffma2(acc[0][cc], h0.x, Vr[cc][2 * i]);
                ffma2(acc[0][cc], h0.y, Vr[cc][2 * i + 1]);
                ffma2(acc[1][cc], h1.x, Vr[cc][2 * i]);
                ffma2(acc[1][cc], h1.y, Vr[cc][2 * i + 1]);
            }
        }

        // ---- stage partials: red[t&1][kw][r][cw*128 + 32cc + l]
#pragma unroll
        for (int r = 0; r < 2; r++)
#pragma unroll
            for (int cc = 0; cc < 4; cc++)
                redb[rstore + r * 256 + 32 * cc] = acc_sum(acc[r][cc]);
        __syncthreads();                      // bar#1 (full)

        // ---- finalize: 8-way reduce over kw', tanh, store
        float s = 0.f;
#pragma unroll
        for (int ww = 0; ww < 8; ww++)
            s += redb[ww * 512 + fr * 256 + fc];
        const float v = tanh_fast(s + xu);

        dec[oBase + (size_t)t * HID] = v;

        const int nxt = cur ^ 1;
        hb[nxt * 512 + fr * 256 + fc] = v;
        bar_named(barid, 64);                 // pair {kw, kw+8}: h[nxt] ready
        cur = nxt;
    }
}

// ---------------------------------------------------------------------------
// launch
// ---------------------------------------------------------------------------
extern "C" void kernel_launch(void* const* d_in, const int* in_sizes, int n_in,
                              void* d_out, int out_size)
{
    const float* enc  = (const float*)d_in[0];
    const float* xdec = (const float*)d_in[1];
    const float* U    = (const float*)d_in[2];
    const float* V    = (const float*)d_in[3];
    const float* b    = (const float*)d_in[4];

    float* out = (float*)d_out;
    float* dec = out + (size_t)BZ * HID;

    xu_kernel<<<dim3((BZ * SEQ) / 128, HID / 128), 256>>>(xdec, U, b, dec);

    cudaFuncSetAttribute(rnn_kernel,
                         cudaFuncAttributeMaxDynamicSharedMemorySize,
                         RNN_SMEM_BYTES);
    rnn_kernel<<<128, 512, RNN_SMEM_BYTES>>>(enc, V, dec, out);
}

// round 14
// speedup vs baseline: 1.3167x; 1.1117x over previous
#include <cuda_runtime.h>
#include <cuda_bf16.h>
#include <cstdint>
#include <cstddef>

#define BZ   256
#define SEQ  512
#define INS  256
#define HID  256

// ---------------------------------------------------------------------------
// generic helpers
// ---------------------------------------------------------------------------
__device__ __forceinline__ void ffma2(unsigned long long &acc,
                                      unsigned long long a,
                                      unsigned long long b) {
    asm volatile("fma.rn.f32x2 %0, %1, %2, %0;" : "+l"(acc) : "l"(a), "l"(b));
}
__device__ __forceinline__ unsigned long long pack2(float x, float y) {
    unsigned long long r;
    asm("mov.b64 %0, {%1, %2};" : "=l"(r) : "f"(x), "f"(y));
    return r;
}
__device__ __forceinline__ float2 unpack2(unsigned long long v) {
    float2 f;
    asm("mov.b64 {%0, %1}, %2;" : "=f"(f.x), "=f"(f.y) : "l"(v));
    return f;
}
__device__ __forceinline__ float acc_sum(unsigned long long v) {
    float2 p = unpack2(v);
    return p.x + p.y;
}
__device__ __forceinline__ float tanh_fast(float x) {
    float e;
    asm("ex2.approx.f32 %0, %1;" : "=f"(e) : "f"(x * 2.8853900817779268f));
    float r;
    asm("rcp.approx.f32 %0, %1;" : "=f"(r) : "f"(e + 1.0f));
    return fmaf(-2.0f, r, 1.0f);
}
__device__ __forceinline__ void bar_named(int id, int nthreads) {
    asm volatile("bar.sync %0, %1;" :: "r"(id), "r"(nthreads) : "memory");
}

// warp-level bf16 MMA (baseline PTX, sm_80+; works on plain sm_103 target)
__device__ __forceinline__ void mma_bf16(float* c, const unsigned* a,
                                         const unsigned* b) {
    asm volatile(
        "mma.sync.aligned.m16n8k16.row.col.f32.bf16.bf16.f32 "
        "{%0,%1,%2,%3}, {%4,%5,%6,%7}, {%8,%9}, {%0,%1,%2,%3};\n"
        : "+f"(c[0]), "+f"(c[1]), "+f"(c[2]), "+f"(c[3])
        : "r"(a[0]), "r"(a[1]), "r"(a[2]), "r"(a[3]), "r"(b[0]), "r"(b[1]));
}

// split two fp32 into packed bf16 hi pair + bf16 lo pair (lo = exact residual)
__device__ __forceinline__ void split2(float x, float y,
                                       unsigned &hi, unsigned &lo) {
    __nv_bfloat16 hx = __float2bfloat16_rn(x);
    __nv_bfloat16 hy = __float2bfloat16_rn(y);
    float lx = x - __bfloat162float(hx);
    float ly = y - __bfloat162float(hy);
    hi = (unsigned)__bfloat16_as_ushort(hx)
       | ((unsigned)__bfloat16_as_ushort(hy) << 16);
    asm("cvt.rn.bf16x2.f32 %0, %1, %2;" : "=r"(lo) : "f"(ly), "f"(lx));
}

// ---------------------------------------------------------------------------
// U prep: split U into bf16 hi/lo, transposed to [n][k] (MMA B is col-major k)
// ---------------------------------------------------------------------------
__device__ __nv_bfloat16 g_Uhi[256 * 256];
__device__ __nv_bfloat16 g_Ulo[256 * 256];

__global__ void uprep_kernel(const float* __restrict__ U) {
    int k = blockIdx.x;
    int n = threadIdx.x;
    float v = U[k * 256 + n];
    __nv_bfloat16 hi = __float2bfloat16_rn(v);
    float lo = v - __bfloat162float(hi);
    g_Uhi[n * 256 + k] = hi;
    g_Ulo[n * 256 + k] = __float2bfloat16_rn(lo);
}

// ---------------------------------------------------------------------------
// Kernel 1: XU = X @ U + bias via warp-MMA bf16 hi/lo split (3 products,
// lo*lo dropped -> rel err ~1e-5). CTA 256 thr, tile 128m x 128n, K chunks
// of 64 (4 chunks, single-buffered). A converted fp32->bf16 in-kernel;
// B pre-split by uprep. SMEM pitch 72 bf16 (144B): fragment loads hit banks
// 4*row + kword = 0..31 exactly -> conflict-free.
// ---------------------------------------------------------------------------
#define APITCH 72
#define XA_HI 0
#define XA_LO 18432
#define XB_HI 36864
#define XB_LO 55296
#define XU_SMEM 73728

__global__ void __launch_bounds__(256, 2)
xu_mma_kernel(const float* __restrict__ X, const float* __restrict__ bias,
              float* __restrict__ C)
{
    extern __shared__ __align__(16) char smem[];
    __nv_bfloat16* Ahi = (__nv_bfloat16*)(smem + XA_HI);
    __nv_bfloat16* Alo = (__nv_bfloat16*)(smem + XA_LO);
    __nv_bfloat16* Bhi = (__nv_bfloat16*)(smem + XB_HI);
    __nv_bfloat16* Blo = (__nv_bfloat16*)(smem + XB_LO);

    const int tid  = threadIdx.x;
    const int lane = tid & 31;
    const int wid  = tid >> 5;
    const int wm   = wid & 1;          // m half (64 rows)
    const int wn   = wid >> 1;         // n quarter (32 cols)
    const int m_base = blockIdx.x * 128;
    const int n_base = blockIdx.y * 128;

    float acc[4][4][4];
#pragma unroll
    for (int mi = 0; mi < 4; mi++)
#pragma unroll
        for (int nj = 0; nj < 4; nj++)
#pragma unroll
            for (int q = 0; q < 4; q++) acc[mi][nj][q] = 0.f;

    const int lr = tid >> 1;           // 0..127: tile row for loads
    const int kh = (tid & 1) * 32;     // k-half within 64-chunk

    for (int kc = 0; kc < 4; kc++) {
        // ---- A tile: X[m_base+lr][kc*64+kh .. +32] fp32 -> bf16 hi/lo
        {
            const float4* xs = (const float4*)
                (X + (size_t)(m_base + lr) * 256 + kc * 64 + kh);
            __nv_bfloat16* ah = Ahi + lr * APITCH + kh;
            __nv_bfloat16* al = Alo + lr * APITCH + kh;
#pragma unroll
            for (int i = 0; i < 8; i++) {
                float4 v = xs[i];
                unsigned h01, l01, h23, l23;
                split2(v.x, v.y, h01, l01);
                split2(v.z, v.w, h23, l23);
                *(unsigned long long*)(ah + i * 4) =
                    (unsigned long long)h01 | ((unsigned long long)h23 << 32);
                *(unsigned long long*)(al + i * 4) =
                    (unsigned long long)l01 | ((unsigned long long)l23 << 32);
            }
        }
        // ---- B tile: g_U{hi,lo}[n_base+lr][kc*64+kh .. +32] copy
        {
            const uint4* bh = (const uint4*)
                (g_Uhi + (size_t)(n_base + lr) * 256 + kc * 64 + kh);
            const uint4* bl = (const uint4*)
                (g_Ulo + (size_t)(n_base + lr) * 256 + kc * 64 + kh);
            uint4* dh = (uint4*)(Bhi + lr * APITCH + kh);
            uint4* dl = (uint4*)(Blo + lr * APITCH + kh);
#pragma unroll
            for (int i = 0; i < 4; i++) { dh[i] = bh[i]; dl[i] = bl[i]; }
        }
        __syncthreads();

        // ---- compute: 4 k16-steps
        const int qr = lane >> 2;          // 0..7
        const int kq = (lane & 3) * 2;     // 0,2,4,6
#pragma unroll
        for (int ks = 0; ks < 4; ks++) {
            const int k0 = ks * 16 + kq;
            unsigned a_hi[4][4], a_lo[4][4];
#pragma unroll
            for (int mi = 0; mi < 4; mi++) {
                const int ra = (wm * 64 + mi * 16 + qr) * APITCH + k0;
                a_hi[mi][0] = *(const unsigned*)&Ahi[ra];
                a_hi[mi][1] = *(const unsigned*)&Ahi[ra + 8 * APITCH];
                a_hi[mi][2] = *(const unsigned*)&Ahi[ra + 8];
                a_hi[mi][3] = *(const unsigned*)&Ahi[ra + 8 * APITCH + 8];
                a_lo[mi][0] = *(const unsigned*)&Alo[ra];
                a_lo[mi][1] = *(const unsigned*)&Alo[ra + 8 * APITCH];
                a_lo[mi][2] = *(const unsigned*)&Alo[ra + 8];
                a_lo[mi][3] = *(const unsigned*)&Alo[ra + 8 * APITCH + 8];
            }
#pragma unroll
            for (int nj = 0; nj < 4; nj++) {
                const int rb = (wn * 32 + nj * 8 + qr) * APITCH + k0;
                unsigned b_hi[2], b_lo[2];
                b_hi[0] = *(const unsigned*)&Bhi[rb];
                b_hi[1] = *(const unsigned*)&Bhi[rb + 8];
                b_lo[0] = *(const unsigned*)&Blo[rb];
                b_lo[1] = *(const unsigned*)&Blo[rb + 8];
#pragma unroll
                for (int mi = 0; mi < 4; mi++) {
                    mma_bf16(acc[mi][nj], a_hi[mi], b_hi);
                    mma_bf16(acc[mi][nj], a_lo[mi], b_hi);
                    mma_bf16(acc[mi][nj], a_hi[mi], b_lo);
                }
            }
        }
        __syncthreads();
    }

    // ---- epilogue: add bias, store (fragment layout m16n8: quads)
    const int qr = lane >> 2;
    const int qc = (lane & 3) * 2;
#pragma unroll
    for (int mi = 0; mi < 4; mi++) {
        const int row0 = m_base + wm * 64 + mi * 16 + qr;
#pragma unroll
        for (int nj = 0; nj < 4; nj++) {
            const int col = n_base + wn * 32 + nj * 8 + qc;
            float2 b2 = *(const float2*)(bias + col);
            float2 o0 = { acc[mi][nj][0] + b2.x, acc[mi][nj][1] + b2.y };
            float2 o1 = { acc[mi][nj][2] + b2.x, acc[mi][nj][3] + b2.y };
            *(float2*)(C + (size_t)row0 * 256 + col) = o0;
            *(float2*)(C + (size_t)(row0 + 8) * 256 + col) = o1;
        }
    }
}

// ---------------------------------------------------------------------------
// Kernel 2: EXACT champion rnn (measured 582us) — do not touch.
// ---------------------------------------------------------------------------
#define KREG 20
#define KSM  12
#define VSM_U64S   (8 * (KSM/2) * 256)
#define RED_HALF   (8 * 2 * 256)
#define RED_FLOATS (2 * RED_HALF)
#define HB_FLOATS  (2 * 2 * 256)
#define RNN_SMEM_BYTES (VSM_U64S * 8 + (RED_FLOATS + HB_FLOATS) * 4)

__global__ void __launch_bounds__(512, 1)
rnn_kernel(const float* __restrict__ enc, const float* __restrict__ V,
           float* __restrict__ dec, float* __restrict__ outenc)
{
    extern __shared__ __align__(16) unsigned long long smem_u64[];
    unsigned long long* Vsm = smem_u64;
    float* red = (float*)(smem_u64 + VSM_U64S);
    float* hb  = red + RED_FLOATS;

    const int tid = threadIdx.x;
    const int l   = tid & 31;
    const int w   = tid >> 5;
    const int kw  = w & 7;
    const int cw  = w >> 3;
    const int b0  = blockIdx.x * 2;
    const int K   = kw * 32;
    const int col = cw * 128 + l;

    unsigned long long Vr[4][KREG / 2];
#pragma unroll
    for (int cc = 0; cc < 4; cc++) {
        const float* Vc = V + (size_t)K * HID + col + 32 * cc;
#pragma unroll
        for (int j = 0; j < KREG / 2; j++)
            Vr[cc][j] = pack2(Vc[(size_t)(2 * j) * HID],
                              Vc[(size_t)(2 * j + 1) * HID]);
    }
    for (int idx = tid; idx < VSM_U64S; idx += 512) {
        int kk  = idx >> 8;
        int c   = idx & 255;
        int kw2 = kk / (KSM / 2);
        int j   = kk % (KSM / 2);
        int k   = kw2 * 32 + KREG + 2 * j;
        Vsm[idx] = pack2(V[(size_t)k * HID + c], V[(size_t)(k + 1) * HID + c]);
    }
    {
        const float ev = enc[(size_t)b0 * HID + tid];
        hb[tid] = ev;
        outenc[(size_t)b0 * HID + tid] = ev;
    }
    __syncthreads();

    const int fr = tid >> 8;
    const int fc = tid & 255;
    const size_t oBase = ((size_t)(b0 + fr) * SEQ) * HID + fc;

    const int rstore = kw * 512 + cw * 128 + l;
    const int barid  = 1 + kw;
    int cur = 0;

#pragma unroll 1
    for (int t = 0; t < SEQ; t++) {
        const float xu = dec[oBase + (size_t)t * HID];

        float* redb = red + (t & 1) * RED_HALF;
        const float* h0p = hb + cur * 512 + K;
        const float* h1p = h0p + 256;

        unsigned long long acc[2][4];
#pragma unroll
        for (int r = 0; r < 2; r++)
#pragma unroll
            for (int cc = 0; cc < 4; cc++) acc[r][cc] = 0ULL;

        const unsigned long long* vsb = Vsm + kw * ((KSM / 2) * 256) + col;
#pragma unroll
        for (int i = 0; i < KSM / 4; i++) {
            ulonglong2 h0 = *(const ulonglong2*)(h0p + KREG + 4 * i);
            ulonglong2 h1 = *(const ulonglong2*)(h1p + KREG + 4 * i);
#pragma unroll
            for (int cc = 0; cc < 4; cc++) {
                unsigned long long v0 = vsb[(2 * i) * 256 + 32 * cc];
                unsigned long long v1 = vsb[(2 * i + 1) * 256 + 32 * cc];
                ffma2(acc[0][cc], h0.x, v0);
                ffma2(acc[0][cc], h0.y, v1);
                ffma2(acc[1][cc], h1.x, v0);
                ffma2(acc[1][cc], h1.y, v1);
            }
        }
#pragma unroll
        for (int i = 0; i < KREG / 4; i++) {
            ulonglong2 h0 = *(const ulonglong2*)(h0p + 4 * i);
            ulonglong2 h1 = *(const ulonglong2*)(h1p + 4 * i);
#pragma unroll
            for (int cc = 0; cc < 4; cc++) {
                ffma2(acc[0][cc], h0.x, Vr[cc][2 * i]);
                ffma2(acc[0][cc], h0.y, Vr[cc][2 * i + 1]);
                ffma2(acc[1][cc], h1.x, Vr[cc][2 * i]);
                ffma2(acc[1][cc], h1.y, Vr[cc][2 * i + 1]);
            }
        }

#pragma unroll
        for (int r = 0; r < 2; r++)
#pragma unroll
            for (int cc = 0; cc < 4; cc++)
                redb[rstore + r * 256 + 32 * cc] = acc_sum(acc[r][cc]);
        __syncthreads();

        float s = 0.f;
#pragma unroll
        for (int ww = 0; ww < 8; ww++)
            s += redb[ww * 512 + fr * 256 + fc];
        const float v = tanh_fast(s + xu);

        dec[oBase + (size_t)t * HID] = v;

        const int nxt = cur ^ 1;
        hb[nxt * 512 + fr * 256 + fc] = v;
        bar_named(barid, 64);
        cur = nxt;
    }
}

// ---------------------------------------------------------------------------
// launch
// ---------------------------------------------------------------------------
extern "C" void kernel_launch(void* const* d_in, const int* in_sizes, int n_in,
                              void* d_out, int out_size)
{
    const float* enc  = (const float*)d_in[0];
    const float* xdec = (const float*)d_in[1];
    const float* U    = (const float*)d_in[2];
    const float* V    = (const float*)d_in[3];
    const float* b    = (const float*)d_in[4];

    float* out = (float*)d_out;
    float* dec = out + (size_t)BZ * HID;

    uprep_kernel<<<256, 256>>>(U);

    cudaFuncSetAttribute(xu_mma_kernel,
                         cudaFuncAttributeMaxDynamicSharedMemorySize, XU_SMEM);
    xu_mma_kernel<<<dim3((BZ * SEQ) / 128, HID / 128), 256, XU_SMEM>>>(
        xdec, b, dec);

    cudaFuncSetAttribute(rnn_kernel,
                         cudaFuncAttributeMaxDynamicSharedMemorySize,
                         RNN_SMEM_BYTES);
    rnn_kernel<<<128, 512, RNN_SMEM_BYTES>>>(enc, V, dec, out);
}